// round 1
// baseline (speedup 1.0000x reference)
#include <cuda_runtime.h>
#include <cstdint>
#include <cstddef>

// Problem constants
#define BSZ 256      // batch
#define TT  512      // time steps
#define EE  256      // input dim
#define HH  256      // hidden dim

// ---------------------------------------------------------------------------
// Phase 1: gates = sigmoid(X @ Wx^T + b),  X:[B*T, E], Wx:[H, E] -> G:[B*T, H]
// Classic SGEMM: 128x128 CTA tile, BK=16, 8x8 register tile, 256 threads,
// register-prefetched global loads overlapped with the 1024-FMA k-tile compute.
// ---------------------------------------------------------------------------
__global__ __launch_bounds__(256, 1) void gates_kernel(
    const float* __restrict__ X, const float* __restrict__ W,
    const float* __restrict__ bias, float* __restrict__ G)
{
    __shared__ float As[16][128];
    __shared__ float Ws[16][128];

    const int tid = threadIdx.x;
    const int bm = blockIdx.x * 128;
    const int bn = blockIdx.y * 128;
    const int tx = tid & 15;         // 0..15 -> n tile
    const int ty = tid >> 4;         // 0..15 -> m tile
    const int lr = tid >> 2;         // 0..63 loader row
    const int lc = (tid & 3) << 2;   // 0,4,8,12 loader col (e offset)

    float acc[8][8];
#pragma unroll
    for (int i = 0; i < 8; ++i)
#pragma unroll
        for (int j = 0; j < 8; ++j) acc[i][j] = 0.0f;

    const float* Xp0 = X + (long)(bm + lr) * EE + lc;
    const float* Xp1 = X + (long)(bm + lr + 64) * EE + lc;
    const float* Wp0 = W + (long)(bn + lr) * EE + lc;
    const float* Wp1 = W + (long)(bn + lr + 64) * EE + lc;

    float4 pa0 = *(const float4*)(Xp0);
    float4 pa1 = *(const float4*)(Xp1);
    float4 pw0 = *(const float4*)(Wp0);
    float4 pw1 = *(const float4*)(Wp1);

#pragma unroll 1
    for (int k0 = 0; k0 < EE; k0 += 16) {
        __syncthreads();  // previous tile fully consumed
        As[lc + 0][lr] = pa0.x; As[lc + 1][lr] = pa0.y;
        As[lc + 2][lr] = pa0.z; As[lc + 3][lr] = pa0.w;
        As[lc + 0][lr + 64] = pa1.x; As[lc + 1][lr + 64] = pa1.y;
        As[lc + 2][lr + 64] = pa1.z; As[lc + 3][lr + 64] = pa1.w;
        Ws[lc + 0][lr] = pw0.x; Ws[lc + 1][lr] = pw0.y;
        Ws[lc + 2][lr] = pw0.z; Ws[lc + 3][lr] = pw0.w;
        Ws[lc + 0][lr + 64] = pw1.x; Ws[lc + 1][lr + 64] = pw1.y;
        Ws[lc + 2][lr + 64] = pw1.z; Ws[lc + 3][lr + 64] = pw1.w;
        __syncthreads();

        if (k0 + 16 < EE) {  // prefetch next k-tile into registers (hides LDG)
            pa0 = *(const float4*)(Xp0 + k0 + 16);
            pa1 = *(const float4*)(Xp1 + k0 + 16);
            pw0 = *(const float4*)(Wp0 + k0 + 16);
            pw1 = *(const float4*)(Wp1 + k0 + 16);
        }

#pragma unroll
        for (int k = 0; k < 16; ++k) {
            float a[8], b[8];
            *(float4*)&a[0] = *(const float4*)&As[k][ty * 8];
            *(float4*)&a[4] = *(const float4*)&As[k][ty * 8 + 4];
            *(float4*)&b[0] = *(const float4*)&Ws[k][tx * 8];
            *(float4*)&b[4] = *(const float4*)&Ws[k][tx * 8 + 4];
#pragma unroll
            for (int i = 0; i < 8; ++i)
#pragma unroll
                for (int j = 0; j < 8; ++j)
                    acc[i][j] = fmaf(a[i], b[j], acc[i][j]);
        }
    }

    // Epilogue: add bias, sigmoid, store (float4-coalesced)
    float bb[8];
#pragma unroll
    for (int j = 0; j < 8; ++j) bb[j] = bias[bn + tx * 8 + j];

#pragma unroll
    for (int i = 0; i < 8; ++i) {
        const long m = bm + ty * 8 + i;
        float v[8];
#pragma unroll
        for (int j = 0; j < 8; ++j) {
            float z = acc[i][j] + bb[j];
            v[j] = 1.0f / (1.0f + __expf(-z));
        }
        float4 o0 = {v[0], v[1], v[2], v[3]};
        float4 o1 = {v[4], v[5], v[6], v[7]};
        *(float4*)(G + m * HH + bn + tx * 8)     = o0;
        *(float4*)(G + m * HH + bn + tx * 8 + 4) = o1;
    }
}

// ---------------------------------------------------------------------------
// Phase 2: MGU recurrence. Batch-parallel persistent kernel.
//   Cluster of 2 CTAs handles NB=4 batches for all 512 steps.
//   CTA rank r owns output rows j in [r*128, r*128+128) and holds those 128
//   rows of Wh (fp32) in SMEM (128 x pitch260 = 130KB, conflict-free LDS.128).
//   Ping-pong h buffers [2][4][256]; each step every thread computes 4 dot
//   products (one per batch) for its j, does tanh+gate update, writes h_new
//   to its own AND the peer CTA's h buffer (st.shared::cluster), then a
//   cluster barrier. Gates are read from `out` (written by phase 1) and h is
//   written over the same location (read strictly precedes the write).
// ---------------------------------------------------------------------------
#define NB 4
#define JH 128
#define WPITCH 260   // 260 floats = 1040B row pitch: 65*16B -> phase stride 1 mod 32 -> conflict-free LDS.128
#define SMEM2 ((JH * WPITCH + 2 * NB * HH) * 4)

__device__ __forceinline__ uint32_t smem_u32(const void* p) {
    uint32_t a;
    asm("{ .reg .u64 t; cvta.to.shared.u64 t, %1; cvt.u32.u64 %0, t; }"
        : "=r"(a) : "l"(p));
    return a;
}

__global__ void __cluster_dims__(2, 1, 1) __launch_bounds__(128, 1)
mgu_scan(const float* __restrict__ Whw, const float* __restrict__ Whb,
         float* out)
{
    extern __shared__ float sm[];
    float* Wsh = sm;                       // [JH][WPITCH]
    float* hsh = sm + JH * WPITCH;         // [2][NB][HH]

    const int tid = threadIdx.x;
    uint32_t rank;
    asm("mov.u32 %0, %%cluster_ctarank;" : "=r"(rank));
    const int jbase = (int)rank * JH;
    const int bbase = (blockIdx.x >> 1) * NB;

    // Load this CTA's half of Wh into smem (pitched)
    for (int idx = tid; idx < JH * HH; idx += 128) {
        int j = idx >> 8;
        int k = idx & 255;
        Wsh[j * WPITCH + k] = Whw[(long)(jbase + j) * HH + k];
    }
    // Zero both h buffers (h0 = 0)
    for (int idx = tid; idx < 2 * NB * HH; idx += 128) hsh[idx] = 0.0f;

    const int j = tid;           // 0..127
    const int jg = jbase + j;    // global hidden index
    const float bias = Whb[jg];

    // Per-batch pointers into out (gates in / h out), at (b, 0, jg)
    float* gp0 = out + (long)(bbase + 0) * TT * HH + jg;
    float* gp1 = out + (long)(bbase + 1) * TT * HH + jg;
    float* gp2 = out + (long)(bbase + 2) * TT * HH + jg;
    float* gp3 = out + (long)(bbase + 3) * TT * HH + jg;

    float h0 = 0.f, h1 = 0.f, h2 = 0.f, h3 = 0.f;
    float g0 = gp0[0], g1 = gp1[0], g2 = gp2[0], g3 = gp3[0];  // gates t=0

    // Peer SMEM base address for DSMEM writes
    uint32_t hsh_l = smem_u32(hsh);
    uint32_t hsh_r;
    asm("mapa.shared::cluster.u32 %0, %1, %2;"
        : "=r"(hsh_r) : "r"(hsh_l), "r"(rank ^ 1u));

    // Both CTAs' W/h init must be visible before step 0
    asm volatile("barrier.cluster.arrive.aligned;" ::: "memory");
    asm volatile("barrier.cluster.wait.aligned;"   ::: "memory");

    const float4* w4 = (const float4*)(Wsh + j * WPITCH);

    int p = 0;
#pragma unroll 1
    for (int t = 0; t < TT; ++t) {
        // Prefetch gates for t+1 (consumed next step; latency hidden by matvec)
        float g0n = 0.f, g1n = 0.f, g2n = 0.f, g3n = 0.f;
        if (t + 1 < TT) {
            const long o = (long)(t + 1) * HH;
            g0n = gp0[o]; g1n = gp1[o]; g2n = gp2[o]; g3n = gp3[o];
        }

        // Matvec: acc[b] = bias + sum_k Wh[jg][k] * h[b][k]
        float a0 = bias, a1 = bias, a2 = bias, a3 = bias;
        const float4* hb0 = (const float4*)(hsh + p * (NB * HH));
        const float4* hb1 = hb0 + 64;
        const float4* hb2 = hb0 + 128;
        const float4* hb3 = hb0 + 192;
#pragma unroll 4
        for (int kk = 0; kk < 64; ++kk) {
            const float4 w  = w4[kk];
            const float4 x0 = hb0[kk];
            const float4 x1 = hb1[kk];
            const float4 x2 = hb2[kk];
            const float4 x3 = hb3[kk];
            a0 = fmaf(w.x, x0.x, a0); a0 = fmaf(w.y, x0.y, a0);
            a0 = fmaf(w.z, x0.z, a0); a0 = fmaf(w.w, x0.w, a0);
            a1 = fmaf(w.x, x1.x, a1); a1 = fmaf(w.y, x1.y, a1);
            a1 = fmaf(w.z, x1.z, a1); a1 = fmaf(w.w, x1.w, a1);
            a2 = fmaf(w.x, x2.x, a2); a2 = fmaf(w.y, x2.y, a2);
            a2 = fmaf(w.z, x2.z, a2); a2 = fmaf(w.w, x2.w, a2);
            a3 = fmaf(w.x, x3.x, a3); a3 = fmaf(w.y, x3.y, a3);
            a3 = fmaf(w.z, x3.z, a3); a3 = fmaf(w.w, x3.w, a3);
        }

        // Elementwise update
        const float t0 = tanhf(a0), t1 = tanhf(a1);
        const float t2 = tanhf(a2), t3 = tanhf(a3);
        h0 = h0 * g0 + (1.0f - g0) * t0;
        h1 = h1 * g1 + (1.0f - g1) * t1;
        h2 = h2 * g2 + (1.0f - g2) * t2;
        h3 = h3 * g3 + (1.0f - g3) * t3;
        g0 = g0n; g1 = g1n; g2 = g2n; g3 = g3n;

        // Store h to output (overwrites the gate slot for this (b,t,jg))
        const long ot = (long)t * HH;
        gp0[ot] = h0; gp1[ot] = h1; gp2[ot] = h2; gp3[ot] = h3;

        // Publish h_new to BOTH h buffers (parity q) at index jg
        const int q = p ^ 1;
        const int base = q * (NB * HH);
        hsh[base + 0 * HH + jg] = h0;
        hsh[base + 1 * HH + jg] = h1;
        hsh[base + 2 * HH + jg] = h2;
        hsh[base + 3 * HH + jg] = h3;
        const uint32_t rb = hsh_r + (uint32_t)(base + jg) * 4u;
        asm volatile("st.shared::cluster.f32 [%0], %1;" :: "r"(rb),            "f"(h0) : "memory");
        asm volatile("st.shared::cluster.f32 [%0], %1;" :: "r"(rb + 1024u),    "f"(h1) : "memory");
        asm volatile("st.shared::cluster.f32 [%0], %1;" :: "r"(rb + 2048u),    "f"(h2) : "memory");
        asm volatile("st.shared::cluster.f32 [%0], %1;" :: "r"(rb + 3072u),    "f"(h3) : "memory");

        // Step barrier: release local+remote smem writes, acquire peer's
        asm volatile("barrier.cluster.arrive.aligned;" ::: "memory");
        asm volatile("barrier.cluster.wait.aligned;"   ::: "memory");
        p = q;
    }
}

// ---------------------------------------------------------------------------
extern "C" void kernel_launch(void* const* d_in, const int* in_sizes, int n_in,
                              void* d_out, int out_size)
{
    const float* x   = (const float*)d_in[0];  // [B,T,E]
    const float* Wxw = (const float*)d_in[1];  // [H,E]
    const float* Wxb = (const float*)d_in[2];  // [H]
    const float* Whw = (const float*)d_in[3];  // [H,H]
    const float* Whb = (const float*)d_in[4];  // [H]
    float* out = (float*)d_out;                // [B,T,H]

    // Phase 1: gates -> out
    dim3 g1(BSZ * TT / 128, HH / 128);
    gates_kernel<<<g1, 256>>>(x, Wxw, Wxb, out);

    // Phase 2: recurrence in-place over out
    cudaFuncSetAttribute(mgu_scan, cudaFuncAttributeMaxDynamicSharedMemorySize,
                         SMEM2);
    mgu_scan<<<BSZ / NB * 2, 128, SMEM2>>>(Whw, Whb, out);
}

// round 2
// speedup vs baseline: 1.3473x; 1.3473x over previous
#include <cuda_runtime.h>
#include <cstdint>
#include <cstddef>

// Problem constants
#define BSZ 256      // batch
#define TT  512      // time steps
#define EE  256      // input dim
#define HH  256      // hidden dim

typedef unsigned long long ull;

// ---- packed f32x2 helpers (Blackwell) -------------------------------------
__device__ __forceinline__ ull fma2(ull a, ull b, ull c) {
    ull d;
    asm("fma.rn.f32x2 %0, %1, %2, %3;" : "=l"(d) : "l"(a), "l"(b), "l"(c));
    return d;
}
__device__ __forceinline__ ull splat2(float x) {
    ull d;
    asm("mov.b64 %0, {%1, %1};" : "=l"(d) : "f"(x));
    return d;
}
__device__ __forceinline__ float2 unpack2(ull a) {
    float2 r;
    asm("mov.b64 {%0, %1}, %2;" : "=f"(r.x), "=f"(r.y) : "l"(a));
    return r;
}
__device__ __forceinline__ uint32_t smem_u32(const void* p) {
    uint32_t a;
    asm("{ .reg .u64 t; cvta.to.shared.u64 t, %1; cvt.u32.u64 %0, t; }"
        : "=r"(a) : "l"(p));
    return a;
}

// ---------------------------------------------------------------------------
// Phase 1: gates = sigmoid(X @ Wx^T + b)  via packed-f32x2 SGEMM.
// 128x128 CTA tile, BK=16, 8x8 register tile (j packed in pairs), 256 thr.
// ---------------------------------------------------------------------------
__global__ __launch_bounds__(256, 2) void gates_kernel(
    const float* __restrict__ X, const float* __restrict__ W,
    const float* __restrict__ bias, float* __restrict__ G)
{
    __shared__ __align__(16) float As[16][128];
    __shared__ __align__(16) float Ws[16][128];

    const int tid = threadIdx.x;
    const int bm = blockIdx.x * 128;
    const int bn = blockIdx.y * 128;
    const int tx = tid & 15;         // n tile
    const int ty = tid >> 4;         // m tile
    const int lr = tid >> 2;         // loader row
    const int lc = (tid & 3) << 2;   // loader col

    ull acc[8][4];
#pragma unroll
    for (int i = 0; i < 8; ++i)
#pragma unroll
        for (int jj = 0; jj < 4; ++jj) acc[i][jj] = 0ull;

    const float* Xp0 = X + (size_t)(bm + lr) * EE + lc;
    const float* Xp1 = X + (size_t)(bm + lr + 64) * EE + lc;
    const float* Wp0 = W + (size_t)(bn + lr) * EE + lc;
    const float* Wp1 = W + (size_t)(bn + lr + 64) * EE + lc;

    float4 pa0 = *(const float4*)(Xp0);
    float4 pa1 = *(const float4*)(Xp1);
    float4 pw0 = *(const float4*)(Wp0);
    float4 pw1 = *(const float4*)(Wp1);

#pragma unroll 1
    for (int k0 = 0; k0 < EE; k0 += 16) {
        __syncthreads();
        As[lc + 0][lr] = pa0.x; As[lc + 1][lr] = pa0.y;
        As[lc + 2][lr] = pa0.z; As[lc + 3][lr] = pa0.w;
        As[lc + 0][lr + 64] = pa1.x; As[lc + 1][lr + 64] = pa1.y;
        As[lc + 2][lr + 64] = pa1.z; As[lc + 3][lr + 64] = pa1.w;
        Ws[lc + 0][lr] = pw0.x; Ws[lc + 1][lr] = pw0.y;
        Ws[lc + 2][lr] = pw0.z; Ws[lc + 3][lr] = pw0.w;
        Ws[lc + 0][lr + 64] = pw1.x; Ws[lc + 1][lr + 64] = pw1.y;
        Ws[lc + 2][lr + 64] = pw1.z; Ws[lc + 3][lr + 64] = pw1.w;
        __syncthreads();

        if (k0 + 16 < EE) {
            pa0 = *(const float4*)(Xp0 + k0 + 16);
            pa1 = *(const float4*)(Xp1 + k0 + 16);
            pw0 = *(const float4*)(Wp0 + k0 + 16);
            pw1 = *(const float4*)(Wp1 + k0 + 16);
        }

#pragma unroll
        for (int k = 0; k < 16; ++k) {
            float a[8];
            *(float4*)&a[0] = *(const float4*)&As[k][ty * 8];
            *(float4*)&a[4] = *(const float4*)&As[k][ty * 8 + 4];
            ulonglong2 u0 = *(const ulonglong2*)&Ws[k][tx * 8];
            ulonglong2 u1 = *(const ulonglong2*)&Ws[k][tx * 8 + 4];
            const ull b0 = u0.x, b1 = u0.y, b2 = u1.x, b3 = u1.y;
#pragma unroll
            for (int i = 0; i < 8; ++i) {
                const ull s = splat2(a[i]);
                acc[i][0] = fma2(s, b0, acc[i][0]);
                acc[i][1] = fma2(s, b1, acc[i][1]);
                acc[i][2] = fma2(s, b2, acc[i][2]);
                acc[i][3] = fma2(s, b3, acc[i][3]);
            }
        }
    }

    // Epilogue: unpack, +bias, sigmoid, float4 stores
    float bb[8];
#pragma unroll
    for (int jj = 0; jj < 8; ++jj) bb[jj] = bias[bn + tx * 8 + jj];

#pragma unroll
    for (int i = 0; i < 8; ++i) {
        const size_t m = bm + ty * 8 + i;
        float v[8];
#pragma unroll
        for (int jj = 0; jj < 4; ++jj) {
            float2 z = unpack2(acc[i][jj]);
            float z0 = z.x + bb[2 * jj];
            float z1 = z.y + bb[2 * jj + 1];
            v[2 * jj]     = 1.0f / (1.0f + __expf(-z0));
            v[2 * jj + 1] = 1.0f / (1.0f + __expf(-z1));
        }
        float4 o0 = {v[0], v[1], v[2], v[3]};
        float4 o1 = {v[4], v[5], v[6], v[7]};
        *(float4*)(G + m * HH + bn + tx * 8)     = o0;
        *(float4*)(G + m * HH + bn + tx * 8 + 4) = o1;
    }
}

// ---------------------------------------------------------------------------
// Phase 2: MGU recurrence, W-in-registers, packed f32x2 matvec.
//   Cluster of 2 CTAs = 4 batches x 512 steps. CTA rank r owns j in
//   [r*128, r*128+128). 256 threads: j = tid&127, khalf = tid>>7.
//   Each thread holds 128 W floats (its j row, its K half) as 64 packed regs.
//   Per step: packed matvec over smem h (broadcast ld.shared.v2.u64),
//   K-half reduction via tiny smem, tanh+gate update by khalf==0 threads,
//   h published to local + peer (DSMEM) ping-pong buffer, cluster barrier.
//   Gates live in `out` and are overwritten by h (read precedes write).
// ---------------------------------------------------------------------------
#define NB 4

__global__ void __cluster_dims__(2, 1, 1) __launch_bounds__(256, 1)
mgu_scan(const float* __restrict__ Whw, const float* __restrict__ Whb,
         float* out)
{
    __shared__ __align__(16) float hsh[2 * NB * HH];   // 8 KB ping-pong h
    __shared__ __align__(16) float psum[NB][128];      // 2 KB K-half partials

    const int tid = threadIdx.x;
    const int j  = tid & 127;
    const int kh = tid >> 7;
    uint32_t rank;
    asm("mov.u32 %0, %%cluster_ctarank;" : "=r"(rank));
    const int jg = (int)rank * 128 + j;
    const int bbase = (blockIdx.x >> 1) * NB;

    // --- W row (this j, this K half) into 64 packed registers ---
    ull wv[64];
    {
        const ulonglong2* wp =
            (const ulonglong2*)(Whw + (size_t)jg * HH + kh * 128);
#pragma unroll
        for (int i = 0; i < 32; ++i) {
            ulonglong2 v = wp[i];
            wv[2 * i] = v.x; wv[2 * i + 1] = v.y;
        }
    }

    for (int i = tid; i < 2 * NB * HH; i += 256) hsh[i] = 0.0f;

    float* gb0 = out + (size_t)(bbase + 0) * TT * HH + jg;
    float* gb1 = out + (size_t)(bbase + 1) * TT * HH + jg;
    float* gb2 = out + (size_t)(bbase + 2) * TT * HH + jg;
    float* gb3 = out + (size_t)(bbase + 3) * TT * HH + jg;

    float bias = 0.f;
    float h0 = 0.f, h1 = 0.f, h2 = 0.f, h3 = 0.f;
    float g0 = 0.f, g1 = 0.f, g2 = 0.f, g3 = 0.f;
    if (kh == 0) {
        bias = Whb[jg];
        g0 = gb0[0]; g1 = gb1[0]; g2 = gb2[0]; g3 = gb3[0];
    }

    const uint32_t hl = smem_u32(hsh);
    uint32_t hr;
    asm("mapa.shared::cluster.u32 %0, %1, %2;"
        : "=r"(hr) : "r"(hl), "r"(rank ^ 1u));

    asm volatile("barrier.cluster.arrive.aligned;" ::: "memory");
    asm volatile("barrier.cluster.wait.aligned;"   ::: "memory");

    int p = 0;
#pragma unroll 1
    for (int t = 0; t < TT; ++t) {
        // prefetch next-step gates (latency hidden by the matvec)
        float g0n = 0.f, g1n = 0.f, g2n = 0.f, g3n = 0.f;
        if (kh == 0 && t + 1 < TT) {
            const size_t o = (size_t)(t + 1) * HH;
            g0n = gb0[o]; g1n = gb1[o]; g2n = gb2[o]; g3n = gb3[o];
        }

        // packed matvec over this thread's K half
        const float* hb = hsh + p * (NB * HH) + kh * 128;
        const ulonglong2* x0 = (const ulonglong2*)(hb);
        const ulonglong2* x1 = (const ulonglong2*)(hb + HH);
        const ulonglong2* x2 = (const ulonglong2*)(hb + 2 * HH);
        const ulonglong2* x3 = (const ulonglong2*)(hb + 3 * HH);
        ull a0 = 0ull, a1 = 0ull, a2 = 0ull, a3 = 0ull;
#pragma unroll
        for (int kk = 0; kk < 32; ++kk) {
            const ulonglong2 v0 = x0[kk];
            const ulonglong2 v1 = x1[kk];
            const ulonglong2 v2 = x2[kk];
            const ulonglong2 v3 = x3[kk];
            const ull wA = wv[2 * kk], wB = wv[2 * kk + 1];
            a0 = fma2(wA, v0.x, a0);
            a1 = fma2(wA, v1.x, a1);
            a2 = fma2(wA, v2.x, a2);
            a3 = fma2(wA, v3.x, a3);
            a0 = fma2(wB, v0.y, a0);
            a1 = fma2(wB, v1.y, a1);
            a2 = fma2(wB, v2.y, a2);
            a3 = fma2(wB, v3.y, a3);
        }
        const float2 s0 = unpack2(a0), s1 = unpack2(a1);
        const float2 s2 = unpack2(a2), s3 = unpack2(a3);
        const float r0 = s0.x + s0.y, r1 = s1.x + s1.y;
        const float r2 = s2.x + s2.y, r3 = s3.x + s3.y;

        if (kh) {
            psum[0][j] = r0; psum[1][j] = r1;
            psum[2][j] = r2; psum[3][j] = r3;
        }
        __syncthreads();

        const int q = p ^ 1;
        if (!kh) {
            const float z0 = r0 + psum[0][j] + bias;
            const float z1 = r1 + psum[1][j] + bias;
            const float z2 = r2 + psum[2][j] + bias;
            const float z3 = r3 + psum[3][j] + bias;
            const float t0 = tanhf(z0), t1 = tanhf(z1);
            const float t2 = tanhf(z2), t3 = tanhf(z3);
            h0 = h0 * g0 + (1.0f - g0) * t0;
            h1 = h1 * g1 + (1.0f - g1) * t1;
            h2 = h2 * g2 + (1.0f - g2) * t2;
            h3 = h3 * g3 + (1.0f - g3) * t3;
            g0 = g0n; g1 = g1n; g2 = g2n; g3 = g3n;

            const size_t ot = (size_t)t * HH;
            gb0[ot] = h0; gb1[ot] = h1; gb2[ot] = h2; gb3[ot] = h3;

            const int base = q * (NB * HH);
            hsh[base + 0 * HH + jg] = h0;
            hsh[base + 1 * HH + jg] = h1;
            hsh[base + 2 * HH + jg] = h2;
            hsh[base + 3 * HH + jg] = h3;
            const uint32_t rb = hr + (uint32_t)(base + jg) * 4u;
            asm volatile("st.shared::cluster.f32 [%0], %1;" :: "r"(rb),         "f"(h0) : "memory");
            asm volatile("st.shared::cluster.f32 [%0], %1;" :: "r"(rb + 1024u), "f"(h1) : "memory");
            asm volatile("st.shared::cluster.f32 [%0], %1;" :: "r"(rb + 2048u), "f"(h2) : "memory");
            asm volatile("st.shared::cluster.f32 [%0], %1;" :: "r"(rb + 3072u), "f"(h3) : "memory");
        }

        asm volatile("barrier.cluster.arrive.aligned;" ::: "memory");
        asm volatile("barrier.cluster.wait.aligned;"   ::: "memory");
        p = q;
    }
}

// ---------------------------------------------------------------------------
extern "C" void kernel_launch(void* const* d_in, const int* in_sizes, int n_in,
                              void* d_out, int out_size)
{
    const float* x   = (const float*)d_in[0];  // [B,T,E]
    const float* Wxw = (const float*)d_in[1];  // [H,E]
    const float* Wxb = (const float*)d_in[2];  // [H]
    const float* Whw = (const float*)d_in[3];  // [H,H]
    const float* Whb = (const float*)d_in[4];  // [H]
    float* out = (float*)d_out;                // [B,T,H]

    // Phase 1: gates -> out
    dim3 g1(BSZ * TT / 128, HH / 128);
    gates_kernel<<<g1, 256>>>(x, Wxw, Wxb, out);

    // Phase 2: recurrence in-place over out
    mgu_scan<<<(BSZ / NB) * 2, 256>>>(Whw, Whb, out);
}

// round 4
// speedup vs baseline: 1.3706x; 1.0173x over previous
#include <cuda_runtime.h>
#include <cstdint>
#include <cstddef>

// Problem constants
#define BSZ 256      // batch
#define TT  512      // time steps
#define EE  256      // input dim
#define HH  256      // hidden dim
#define NB  4        // batches per cluster

typedef unsigned long long ull;

// ---- packed f32x2 helpers (Blackwell) -------------------------------------
__device__ __forceinline__ ull fma2(ull a, ull b, ull c) {
    ull d;
    asm("fma.rn.f32x2 %0, %1, %2, %3;" : "=l"(d) : "l"(a), "l"(b), "l"(c));
    return d;
}
__device__ __forceinline__ ull splat2(float x) {
    ull d;
    asm("mov.b64 %0, {%1, %1};" : "=l"(d) : "f"(x));
    return d;
}
__device__ __forceinline__ float2 unpack2(ull a) {
    float2 r;
    asm("mov.b64 {%0, %1}, %2;" : "=f"(r.x), "=f"(r.y) : "l"(a));
    return r;
}
__device__ __forceinline__ uint32_t smem_u32(const void* p) {
    uint32_t a;
    asm("{ .reg .u64 t; cvta.to.shared.u64 t, %1; cvt.u32.u64 %0, t; }"
        : "=r"(a) : "l"(p));
    return a;
}
// fast tanh via MUFU exp: (e^{2z}-1)/(e^{2z}+1); |z| <~ 12 here, no overflow
__device__ __forceinline__ float ftanh(float z) {
    float e = __expf(2.0f * z);
    return __fdividef(e - 1.0f, e + 1.0f);
}

// ---------------------------------------------------------------------------
// Phase 1: gates = sigmoid(X @ Wx^T + b)  via packed-f32x2 SGEMM.
// ---------------------------------------------------------------------------
__global__ __launch_bounds__(256, 2) void gates_kernel(
    const float* __restrict__ X, const float* __restrict__ W,
    const float* __restrict__ bias, float* __restrict__ G)
{
    __shared__ __align__(16) float As[16][128];
    __shared__ __align__(16) float Ws[16][128];

    const int tid = threadIdx.x;
    const int bm = blockIdx.x * 128;
    const int bn = blockIdx.y * 128;
    const int tx = tid & 15;
    const int ty = tid >> 4;
    const int lr = tid >> 2;
    const int lc = (tid & 3) << 2;

    ull acc[8][4];
#pragma unroll
    for (int i = 0; i < 8; ++i)
#pragma unroll
        for (int jj = 0; jj < 4; ++jj) acc[i][jj] = 0ull;

    const float* Xp0 = X + (size_t)(bm + lr) * EE + lc;
    const float* Xp1 = X + (size_t)(bm + lr + 64) * EE + lc;
    const float* Wp0 = W + (size_t)(bn + lr) * EE + lc;
    const float* Wp1 = W + (size_t)(bn + lr + 64) * EE + lc;

    float4 pa0 = *(const float4*)(Xp0);
    float4 pa1 = *(const float4*)(Xp1);
    float4 pw0 = *(const float4*)(Wp0);
    float4 pw1 = *(const float4*)(Wp1);

#pragma unroll 1
    for (int k0 = 0; k0 < EE; k0 += 16) {
        __syncthreads();
        As[lc + 0][lr] = pa0.x; As[lc + 1][lr] = pa0.y;
        As[lc + 2][lr] = pa0.z; As[lc + 3][lr] = pa0.w;
        As[lc + 0][lr + 64] = pa1.x; As[lc + 1][lr + 64] = pa1.y;
        As[lc + 2][lr + 64] = pa1.z; As[lc + 3][lr + 64] = pa1.w;
        Ws[lc + 0][lr] = pw0.x; Ws[lc + 1][lr] = pw0.y;
        Ws[lc + 2][lr] = pw0.z; Ws[lc + 3][lr] = pw0.w;
        Ws[lc + 0][lr + 64] = pw1.x; Ws[lc + 1][lr + 64] = pw1.y;
        Ws[lc + 2][lr + 64] = pw1.z; Ws[lc + 3][lr + 64] = pw1.w;
        __syncthreads();

        if (k0 + 16 < EE) {
            pa0 = *(const float4*)(Xp0 + k0 + 16);
            pa1 = *(const float4*)(Xp1 + k0 + 16);
            pw0 = *(const float4*)(Wp0 + k0 + 16);
            pw1 = *(const float4*)(Wp1 + k0 + 16);
        }

#pragma unroll
        for (int k = 0; k < 16; ++k) {
            float a[8];
            *(float4*)&a[0] = *(const float4*)&As[k][ty * 8];
            *(float4*)&a[4] = *(const float4*)&As[k][ty * 8 + 4];
            ulonglong2 u0 = *(const ulonglong2*)&Ws[k][tx * 8];
            ulonglong2 u1 = *(const ulonglong2*)&Ws[k][tx * 8 + 4];
            const ull b0 = u0.x, b1 = u0.y, b2 = u1.x, b3 = u1.y;
#pragma unroll
            for (int i = 0; i < 8; ++i) {
                const ull s = splat2(a[i]);
                acc[i][0] = fma2(s, b0, acc[i][0]);
                acc[i][1] = fma2(s, b1, acc[i][1]);
                acc[i][2] = fma2(s, b2, acc[i][2]);
                acc[i][3] = fma2(s, b3, acc[i][3]);
            }
        }
    }

    float bb[8];
#pragma unroll
    for (int jj = 0; jj < 8; ++jj) bb[jj] = bias[bn + tx * 8 + jj];

#pragma unroll
    for (int i = 0; i < 8; ++i) {
        const size_t m = bm + ty * 8 + i;
        float v[8];
#pragma unroll
        for (int jj = 0; jj < 4; ++jj) {
            float2 z = unpack2(acc[i][jj]);
            float z0 = z.x + bb[2 * jj];
            float z1 = z.y + bb[2 * jj + 1];
            v[2 * jj]     = 1.0f / (1.0f + __expf(-z0));
            v[2 * jj + 1] = 1.0f / (1.0f + __expf(-z1));
        }
        float4 o0 = {v[0], v[1], v[2], v[3]};
        float4 o1 = {v[4], v[5], v[6], v[7]};
        *(float4*)(G + m * HH + bn + tx * 8)     = o0;
        *(float4*)(G + m * HH + bn + tx * 8 + 4) = o1;
    }
}

// ---------------------------------------------------------------------------
// Phase 2: MGU recurrence.
//   Cluster(2) x 64 = 128 CTAs, NB=4 batches per cluster, 512 steps.
//   CTA rank r owns hidden rows [r*128, r*128+128).
//   256 threads: j2 = tid&63 -> rows {jg0=r*128+j2, jg1=jg0+64};
//                kq = tid>>6 -> K-quarter [kq*64, kq*64+64).
//   W in regs (2 rows x 64 k = 64 packed ull); each h LDS.128 feeds 4 FFMA2.
//   Per step: remote-K threads wait peer mbarrier -> matvec -> psum ->
//   __syncthreads -> all threads redundantly reduce + fast-tanh + update ->
//   role stores (kq0: STG out; kq1: local h buf; kq2: peer h via DSMEM) ->
//   __syncthreads -> tid0 arrives local + remote mbarriers.
//   Last step publishes nothing cross-CTA; trailing cluster sync prevents
//   the exit race (peer DSMEM traffic in flight when a CTA exits = UB).
// ---------------------------------------------------------------------------
__global__ void __cluster_dims__(2, 1, 1) __launch_bounds__(256, 1)
mgu_scan(const float* __restrict__ Whw, const float* __restrict__ Whb,
         float* out)
{
    __shared__ __align__(16) float hsh[2][NB][HH];     // 8 KB ping-pong h
    __shared__ __align__(16) float psum[32 * 64];      // 8 KB partials
    __shared__ __align__(8)  ull  bars[2];

    const int tid = threadIdx.x;
    const int j2 = tid & 63;
    const int kq = tid >> 6;
    uint32_t rank;
    asm("mov.u32 %0, %%cluster_ctarank;" : "=r"(rank));
    const int jg0 = (int)rank * 128 + j2;
    const int jg1 = jg0 + 64;
    const int bbase = (blockIdx.x >> 1) * NB;
    // K-quarter [kq*64..) holds h-entries produced by CTA (kq>>1)
    const bool remote_k = ((uint32_t)(kq >> 1) != rank);

    // --- W rows (2 j, this K quarter) into 64 packed registers ---
    ull wv0[32], wv1[32];
    {
        const ulonglong2* wp0 =
            (const ulonglong2*)(Whw + (size_t)jg0 * HH + kq * 64);
        const ulonglong2* wp1 =
            (const ulonglong2*)(Whw + (size_t)jg1 * HH + kq * 64);
#pragma unroll
        for (int i = 0; i < 16; ++i) {
            ulonglong2 a = wp0[i], b = wp1[i];
            wv0[2 * i] = a.x; wv0[2 * i + 1] = a.y;
            wv1[2 * i] = b.x; wv1[2 * i + 1] = b.y;
        }
    }

    for (int i = tid; i < 2 * NB * HH; i += 256)
        ((float*)hsh)[i] = 0.0f;

    if (tid == 0) {
        asm volatile("mbarrier.init.shared.b64 [%0], 2;"
                     :: "r"(smem_u32(&bars[0])) : "memory");
        asm volatile("mbarrier.init.shared.b64 [%0], 2;"
                     :: "r"(smem_u32(&bars[1])) : "memory");
    }

    const float bias0 = Whb[jg0];
    const float bias1 = Whb[jg1];

    // gate/out pointers per batch at row jg0 (jg1 = +64)
    float* gb0 = out + (size_t)(bbase + 0) * TT * HH + jg0;
    float* gb1 = out + (size_t)(bbase + 1) * TT * HH + jg0;
    float* gb2 = out + (size_t)(bbase + 2) * TT * HH + jg0;
    float* gb3 = out + (size_t)(bbase + 3) * TT * HH + jg0;

    // gates for t=0 (e = jj*4 + b)
    float g[8];
    g[0] = gb0[0];  g[1] = gb1[0];  g[2] = gb2[0];  g[3] = gb3[0];
    g[4] = gb0[64]; g[5] = gb1[64]; g[6] = gb2[64]; g[7] = gb3[64];

    // cluster addresses
    const uint32_t hl = smem_u32(hsh);
    const uint32_t bl0 = smem_u32(&bars[0]);
    uint32_t hr, br0;
    asm("mapa.shared::cluster.u32 %0, %1, %2;"
        : "=r"(hr) : "r"(hl), "r"(rank ^ 1u));
    asm("mapa.shared::cluster.u32 %0, %1, %2;"
        : "=r"(br0) : "r"(bl0), "r"(rank ^ 1u));

    __syncthreads();
    // one-time: both CTAs' smem init + mbarrier init visible cluster-wide
    asm volatile("barrier.cluster.arrive.aligned;" ::: "memory");
    asm volatile("barrier.cluster.wait.aligned;"   ::: "memory");

    uint32_t ph0 = 0, ph1 = 0;

#pragma unroll 1
    for (int t = 0; t < TT; ++t) {
        const int p = t & 1;
        const int q = p ^ 1;
        const bool not_last = (t + 1 < TT);

        // prefetch gates for t+1
        float gn[8];
        if (not_last) {
            const size_t o = (size_t)(t + 1) * HH;
            gn[0] = gb0[o];      gn[1] = gb1[o];
            gn[2] = gb2[o];      gn[3] = gb3[o];
            gn[4] = gb0[o + 64]; gn[5] = gb1[o + 64];
            gn[6] = gb2[o + 64]; gn[7] = gb3[o + 64];
        } else {
#pragma unroll
            for (int e = 0; e < 8; ++e) gn[e] = 0.0f;
        }

        // remote-K threads wait for peer's h(t) delivery into buffer p
        if (t > 0 && remote_k) {
            const uint32_t mb = bl0 + (uint32_t)p * 8u;
            const uint32_t par = p ? ph1 : ph0;
            uint32_t done;
            do {
                asm volatile(
                    "{\n\t.reg .pred P;\n\t"
                    "mbarrier.try_wait.parity.acquire.cluster.shared::cta.b64 "
                    "P, [%1], %2, 0x989680;\n\t"
                    "selp.b32 %0, 1, 0, P;\n\t}"
                    : "=r"(done) : "r"(mb), "r"(par) : "memory");
            } while (!done);
        }
        if (t > 0) { if (p) ph1 ^= 1; else ph0 ^= 1; }

        // ---- matvec over this thread's K-quarter (ratio 4 fma2 : 1 LDS) ----
        const float* hb = &hsh[p][0][kq * 64];
        ull a00 = 0, a01 = 0, a02 = 0, a03 = 0;   // row jg0, batches 0..3
        ull a10 = 0, a11 = 0, a12 = 0, a13 = 0;   // row jg1
#pragma unroll
        for (int i = 0; i < 16; ++i) {
            const ulonglong2 v0 = ((const ulonglong2*)(hb          ))[i];
            const ulonglong2 v1 = ((const ulonglong2*)(hb + HH     ))[i];
            const ulonglong2 v2 = ((const ulonglong2*)(hb + 2 * HH))[i];
            const ulonglong2 v3 = ((const ulonglong2*)(hb + 3 * HH))[i];
            const ull wA0 = wv0[2 * i], wB0 = wv0[2 * i + 1];
            const ull wA1 = wv1[2 * i], wB1 = wv1[2 * i + 1];
            a00 = fma2(wA0, v0.x, a00); a01 = fma2(wA0, v1.x, a01);
            a02 = fma2(wA0, v2.x, a02); a03 = fma2(wA0, v3.x, a03);
            a10 = fma2(wA1, v0.x, a10); a11 = fma2(wA1, v1.x, a11);
            a12 = fma2(wA1, v2.x, a12); a13 = fma2(wA1, v3.x, a13);
            a00 = fma2(wB0, v0.y, a00); a01 = fma2(wB0, v1.y, a01);
            a02 = fma2(wB0, v2.y, a02); a03 = fma2(wB0, v3.y, a03);
            a10 = fma2(wB1, v0.y, a10); a11 = fma2(wB1, v1.y, a11);
            a12 = fma2(wB1, v2.y, a12); a13 = fma2(wB1, v3.y, a13);
        }
        // pair-sum and publish partials: slot s = kq*8 + e, e = jj*4 + b
        {
            float r[8];
            float2 u;
            u = unpack2(a00); r[0] = u.x + u.y;
            u = unpack2(a01); r[1] = u.x + u.y;
            u = unpack2(a02); r[2] = u.x + u.y;
            u = unpack2(a03); r[3] = u.x + u.y;
            u = unpack2(a10); r[4] = u.x + u.y;
            u = unpack2(a11); r[5] = u.x + u.y;
            u = unpack2(a12); r[6] = u.x + u.y;
            u = unpack2(a13); r[7] = u.x + u.y;
#pragma unroll
            for (int e = 0; e < 8; ++e)
                psum[(kq * 8 + e) * 64 + j2] = r[e];
        }
        __syncthreads();

        // ---- redundant reduce + update on ALL threads ----
        float z[8];
#pragma unroll
        for (int e = 0; e < 8; ++e) {
            float s = psum[e * 64 + j2];          // kq'=0
            s += psum[(8  + e) * 64 + j2];        // kq'=1
            s += psum[(16 + e) * 64 + j2];        // kq'=2
            s += psum[(24 + e) * 64 + j2];        // kq'=3
            z[e] = s + ((e < 4) ? bias0 : bias1);
        }
        float hn[8];
#pragma unroll
        for (int e = 0; e < 8; ++e) {
            const float th = ftanh(z[e]);
            const int joff = (e < 4) ? jg0 : jg1;
            const float hp = hsh[p][e & 3][joff];
            hn[e] = fmaf(g[e], hp - th, th);       // g*h + (1-g)*tanh
        }
#pragma unroll
        for (int e = 0; e < 8; ++e) g[e] = gn[e];

        // ---- role stores ----
        if (kq == 0) {                  // h(t) -> global out (always)
            const size_t ot = (size_t)t * HH;
            gb0[ot] = hn[0]; gb1[ot] = hn[1]; gb2[ot] = hn[2]; gb3[ot] = hn[3];
            gb0[ot + 64] = hn[4]; gb1[ot + 64] = hn[5];
            gb2[ot + 64] = hn[6]; gb3[ot + 64] = hn[7];
        } else if (kq == 1) {           // local h buffer q (next step only)
            if (not_last) {
#pragma unroll
                for (int e = 0; e < 8; ++e)
                    hsh[q][e & 3][(e < 4) ? jg0 : jg1] = hn[e];
            }
        } else if (kq == 2) {           // peer h buffer q via DSMEM
            if (not_last) {
#pragma unroll
                for (int e = 0; e < 8; ++e) {
                    const uint32_t ra = hr +
                        (uint32_t)(((q * NB + (e & 3)) * HH +
                                    ((e < 4) ? jg0 : jg1)) * 4);
                    asm volatile("st.shared::cluster.f32 [%0], %1;"
                                 :: "r"(ra), "f"(hn[e]) : "memory");
                }
            }
        }
        __syncthreads();

        if (tid == 0 && not_last) {  // signal buffer q: local + remote arrive
            const uint32_t off = (uint32_t)q * 8u;
            asm volatile(
                "mbarrier.arrive.release.cluster.shared::cta.b64 _, [%0];"
                :: "r"(bl0 + off) : "memory");
            asm volatile(
                "mbarrier.arrive.release.cluster.shared::cluster.b64 _, [%0];"
                :: "r"(br0 + off) : "memory");
        }
    }

    // Trailing cluster sync: no CTA exits while peer DSMEM traffic may be
    // in flight toward it (exit race = unspecified launch failure).
    asm volatile("barrier.cluster.arrive.aligned;" ::: "memory");
    asm volatile("barrier.cluster.wait.aligned;"   ::: "memory");
}

// ---------------------------------------------------------------------------
extern "C" void kernel_launch(void* const* d_in, const int* in_sizes, int n_in,
                              void* d_out, int out_size)
{
    const float* x   = (const float*)d_in[0];  // [B,T,E]
    const float* Wxw = (const float*)d_in[1];  // [H,E]
    const float* Wxb = (const float*)d_in[2];  // [H]
    const float* Whw = (const float*)d_in[3];  // [H,H]
    const float* Whb = (const float*)d_in[4];  // [H]
    float* out = (float*)d_out;                // [B,T,H]

    dim3 g1(BSZ * TT / 128, HH / 128);
    gates_kernel<<<g1, 256>>>(x, Wxw, Wxb, out);

    mgu_scan<<<(BSZ / NB) * 2, 256>>>(Whw, Whb, out);
}

// round 5
// speedup vs baseline: 1.4634x; 1.0677x over previous
#include <cuda_runtime.h>
#include <cstdint>
#include <cstddef>

// Problem constants
#define BSZ 256      // batch
#define TT  512      // time steps
#define EE  256      // input dim
#define HH  256      // hidden dim
#define NB  4        // batches per cluster

typedef unsigned long long ull;

// ---- packed f32x2 helpers (Blackwell) -------------------------------------
__device__ __forceinline__ ull fma2(ull a, ull b, ull c) {
    ull d;
    asm("fma.rn.f32x2 %0, %1, %2, %3;" : "=l"(d) : "l"(a), "l"(b), "l"(c));
    return d;
}
__device__ __forceinline__ ull splat2(float x) {
    ull d;
    asm("mov.b64 %0, {%1, %1};" : "=l"(d) : "f"(x));
    return d;
}
__device__ __forceinline__ float2 unpack2(ull a) {
    float2 r;
    asm("mov.b64 {%0, %1}, %2;" : "=f"(r.x), "=f"(r.y) : "l"(a));
    return r;
}
__device__ __forceinline__ uint32_t smem_u32(const void* p) {
    uint32_t a;
    asm("{ .reg .u64 t; cvta.to.shared.u64 t, %1; cvt.u32.u64 %0, t; }"
        : "=r"(a) : "l"(p));
    return a;
}
// fast tanh via MUFU exp: (e^{2z}-1)/(e^{2z}+1); |z| <~ 12 here, no overflow
__device__ __forceinline__ float ftanh(float z) {
    float e = __expf(2.0f * z);
    return __fdividef(e - 1.0f, e + 1.0f);
}

// ---------------------------------------------------------------------------
// Phase 1: gates = sigmoid(X @ Wx^T + b)  via packed-f32x2 SGEMM. (unchanged)
// ---------------------------------------------------------------------------
__global__ __launch_bounds__(256, 2) void gates_kernel(
    const float* __restrict__ X, const float* __restrict__ W,
    const float* __restrict__ bias, float* __restrict__ G)
{
    __shared__ __align__(16) float As[16][128];
    __shared__ __align__(16) float Ws[16][128];

    const int tid = threadIdx.x;
    const int bm = blockIdx.x * 128;
    const int bn = blockIdx.y * 128;
    const int tx = tid & 15;
    const int ty = tid >> 4;
    const int lr = tid >> 2;
    const int lc = (tid & 3) << 2;

    ull acc[8][4];
#pragma unroll
    for (int i = 0; i < 8; ++i)
#pragma unroll
        for (int jj = 0; jj < 4; ++jj) acc[i][jj] = 0ull;

    const float* Xp0 = X + (size_t)(bm + lr) * EE + lc;
    const float* Xp1 = X + (size_t)(bm + lr + 64) * EE + lc;
    const float* Wp0 = W + (size_t)(bn + lr) * EE + lc;
    const float* Wp1 = W + (size_t)(bn + lr + 64) * EE + lc;

    float4 pa0 = *(const float4*)(Xp0);
    float4 pa1 = *(const float4*)(Xp1);
    float4 pw0 = *(const float4*)(Wp0);
    float4 pw1 = *(const float4*)(Wp1);

#pragma unroll 1
    for (int k0 = 0; k0 < EE; k0 += 16) {
        __syncthreads();
        As[lc + 0][lr] = pa0.x; As[lc + 1][lr] = pa0.y;
        As[lc + 2][lr] = pa0.z; As[lc + 3][lr] = pa0.w;
        As[lc + 0][lr + 64] = pa1.x; As[lc + 1][lr + 64] = pa1.y;
        As[lc + 2][lr + 64] = pa1.z; As[lc + 3][lr + 64] = pa1.w;
        Ws[lc + 0][lr] = pw0.x; Ws[lc + 1][lr] = pw0.y;
        Ws[lc + 2][lr] = pw0.z; Ws[lc + 3][lr] = pw0.w;
        Ws[lc + 0][lr + 64] = pw1.x; Ws[lc + 1][lr + 64] = pw1.y;
        Ws[lc + 2][lr + 64] = pw1.z; Ws[lc + 3][lr + 64] = pw1.w;
        __syncthreads();

        if (k0 + 16 < EE) {
            pa0 = *(const float4*)(Xp0 + k0 + 16);
            pa1 = *(const float4*)(Xp1 + k0 + 16);
            pw0 = *(const float4*)(Wp0 + k0 + 16);
            pw1 = *(const float4*)(Wp1 + k0 + 16);
        }

#pragma unroll
        for (int k = 0; k < 16; ++k) {
            float a[8];
            *(float4*)&a[0] = *(const float4*)&As[k][ty * 8];
            *(float4*)&a[4] = *(const float4*)&As[k][ty * 8 + 4];
            ulonglong2 u0 = *(const ulonglong2*)&Ws[k][tx * 8];
            ulonglong2 u1 = *(const ulonglong2*)&Ws[k][tx * 8 + 4];
            const ull b0 = u0.x, b1 = u0.y, b2 = u1.x, b3 = u1.y;
#pragma unroll
            for (int i = 0; i < 8; ++i) {
                const ull s = splat2(a[i]);
                acc[i][0] = fma2(s, b0, acc[i][0]);
                acc[i][1] = fma2(s, b1, acc[i][1]);
                acc[i][2] = fma2(s, b2, acc[i][2]);
                acc[i][3] = fma2(s, b3, acc[i][3]);
            }
        }
    }

    float bb[8];
#pragma unroll
    for (int jj = 0; jj < 8; ++jj) bb[jj] = bias[bn + tx * 8 + jj];

#pragma unroll
    for (int i = 0; i < 8; ++i) {
        const size_t m = bm + ty * 8 + i;
        float v[8];
#pragma unroll
        for (int jj = 0; jj < 4; ++jj) {
            float2 z = unpack2(acc[i][jj]);
            float z0 = z.x + bb[2 * jj];
            float z1 = z.y + bb[2 * jj + 1];
            v[2 * jj]     = 1.0f / (1.0f + __expf(-z0));
            v[2 * jj + 1] = 1.0f / (1.0f + __expf(-z1));
        }
        float4 o0 = {v[0], v[1], v[2], v[3]};
        float4 o1 = {v[4], v[5], v[6], v[7]};
        *(float4*)(G + m * HH + bn + tx * 8)     = o0;
        *(float4*)(G + m * HH + bn + tx * 8 + 4) = o1;
    }
}

// ---------------------------------------------------------------------------
// Phase 2: MGU recurrence.
//   Cluster(2) x 64 = 128 CTAs, NB=4 batches per cluster, 512 steps.
//   CTA rank r owns hidden rows [r*128, r*128+128).
//   256 threads: j2 = tid&63 -> rows {jg0=r*128+j2, jg1=jg0+64};
//                kq = tid>>6 -> K-quarter [kq*64, kq*64+64).
//   W in regs (2 rows x 64 k = 64 packed ull); each h LDS.128 feeds 4 FFMA2.
//   Per step: remote-K threads wait peer mbarrier -> matvec -> psum[e][j2][kq]
//   -> __syncthreads -> ASSIGNED update: thread (j2,kq) reduces values
//   e in {2kq, 2kq+1} with 2x LDS.128 + 2 fast-tanh, then does its own 3-way
//   stores (STG out, local h buf STS, peer h via DSMEM) -> __syncthreads ->
//   tid0 arrives local + remote mbarriers. Last step publishes nothing
//   cross-CTA; trailing cluster sync prevents the exit race.
// ---------------------------------------------------------------------------
__global__ void __cluster_dims__(2, 1, 1) __launch_bounds__(256, 1)
mgu_scan(const float* __restrict__ Whw, const float* __restrict__ Whb,
         float* out)
{
    __shared__ __align__(16) float hsh[2][NB][HH];      // 8 KB ping-pong h
    __shared__ __align__(16) float psum[8 * 64 * 4];    // 8 KB [e][j2][kq]
    __shared__ __align__(8)  ull  bars[2];

    const int tid = threadIdx.x;
    const int j2 = tid & 63;
    const int kq = tid >> 6;
    uint32_t rank;
    asm("mov.u32 %0, %%cluster_ctarank;" : "=r"(rank));
    const int jg0 = (int)rank * 128 + j2;
    const int jg1 = jg0 + 64;
    const int bbase = (blockIdx.x >> 1) * NB;
    // K-quarter [kq*64..) holds h-entries produced by CTA (kq>>1)
    const bool remote_k = ((uint32_t)(kq >> 1) != rank);

    // --- W rows (2 j, this K quarter) into 64 packed registers ---
    ull wv0[32], wv1[32];
    {
        const ulonglong2* wp0 =
            (const ulonglong2*)(Whw + (size_t)jg0 * HH + kq * 64);
        const ulonglong2* wp1 =
            (const ulonglong2*)(Whw + (size_t)jg1 * HH + kq * 64);
#pragma unroll
        for (int i = 0; i < 16; ++i) {
            ulonglong2 a = wp0[i], b = wp1[i];
            wv0[2 * i] = a.x; wv0[2 * i + 1] = a.y;
            wv1[2 * i] = b.x; wv1[2 * i + 1] = b.y;
        }
    }

    for (int i = tid; i < 2 * NB * HH; i += 256)
        ((float*)hsh)[i] = 0.0f;

    if (tid == 0) {
        asm volatile("mbarrier.init.shared.b64 [%0], 2;"
                     :: "r"(smem_u32(&bars[0])) : "memory");
        asm volatile("mbarrier.init.shared.b64 [%0], 2;"
                     :: "r"(smem_u32(&bars[1])) : "memory");
    }

    // ---- assigned update identity: this thread owns e0=2kq, e0+1 ----
    // e = rowhalf*4 + b  (rowhalf: 0 -> jg0, 1 -> jg1)
    const int e0 = 2 * kq;
    const int rowhalf = kq >> 1;
    const int jrow = rowhalf ? jg1 : jg0;
    const int b0 = e0 & 3;           // batches b0, b0+1
    const float biasr = Whb[jrow];

    // out pointers for the 2 owned (batch,row) streams
    float* po0 = out + (size_t)(bbase + b0)     * TT * HH + jrow;
    float* po1 = out + (size_t)(bbase + b0 + 1) * TT * HH + jrow;

    // gates for t=0
    float gc0 = po0[0], gc1 = po1[0];

    // cluster addresses
    const uint32_t hl = smem_u32(hsh);
    const uint32_t bl0 = smem_u32(&bars[0]);
    uint32_t hr, br0;
    asm("mapa.shared::cluster.u32 %0, %1, %2;"
        : "=r"(hr) : "r"(hl), "r"(rank ^ 1u));
    asm("mapa.shared::cluster.u32 %0, %1, %2;"
        : "=r"(br0) : "r"(bl0), "r"(rank ^ 1u));

    __syncthreads();
    // one-time: both CTAs' smem init + mbarrier init visible cluster-wide
    asm volatile("barrier.cluster.arrive.aligned;" ::: "memory");
    asm volatile("barrier.cluster.wait.aligned;"   ::: "memory");

    uint32_t ph0 = 0, ph1 = 0;

#pragma unroll 1
    for (int t = 0; t < TT; ++t) {
        const int p = t & 1;
        const int q = p ^ 1;
        const bool not_last = (t + 1 < TT);

        // prefetch gates for t+1 (issued before any waiting)
        float gn0 = 0.f, gn1 = 0.f;
        if (not_last) {
            const size_t o = (size_t)(t + 1) * HH;
            gn0 = po0[o]; gn1 = po1[o];
        }

        // remote-K threads wait for peer's h(t) delivery into buffer p
        if (t > 0 && remote_k) {
            const uint32_t mb = bl0 + (uint32_t)p * 8u;
            const uint32_t par = p ? ph1 : ph0;
            uint32_t done;
            do {
                asm volatile(
                    "{\n\t.reg .pred P;\n\t"
                    "mbarrier.try_wait.parity.acquire.cluster.shared::cta.b64 "
                    "P, [%1], %2, 0x989680;\n\t"
                    "selp.b32 %0, 1, 0, P;\n\t}"
                    : "=r"(done) : "r"(mb), "r"(par) : "memory");
            } while (!done);
        }
        if (t > 0) { if (p) ph1 ^= 1; else ph0 ^= 1; }

        // ---- matvec over this thread's K-quarter (ratio 4 fma2 : 1 LDS) ----
        const float* hb = &hsh[p][0][kq * 64];
        ull a00 = 0, a01 = 0, a02 = 0, a03 = 0;   // row jg0, batches 0..3
        ull a10 = 0, a11 = 0, a12 = 0, a13 = 0;   // row jg1
#pragma unroll
        for (int i = 0; i < 16; ++i) {
            const ulonglong2 v0 = ((const ulonglong2*)(hb          ))[i];
            const ulonglong2 v1 = ((const ulonglong2*)(hb + HH     ))[i];
            const ulonglong2 v2 = ((const ulonglong2*)(hb + 2 * HH))[i];
            const ulonglong2 v3 = ((const ulonglong2*)(hb + 3 * HH))[i];
            const ull wA0 = wv0[2 * i], wB0 = wv0[2 * i + 1];
            const ull wA1 = wv1[2 * i], wB1 = wv1[2 * i + 1];
            a00 = fma2(wA0, v0.x, a00); a01 = fma2(wA0, v1.x, a01);
            a02 = fma2(wA0, v2.x, a02); a03 = fma2(wA0, v3.x, a03);
            a10 = fma2(wA1, v0.x, a10); a11 = fma2(wA1, v1.x, a11);
            a12 = fma2(wA1, v2.x, a12); a13 = fma2(wA1, v3.x, a13);
            a00 = fma2(wB0, v0.y, a00); a01 = fma2(wB0, v1.y, a01);
            a02 = fma2(wB0, v2.y, a02); a03 = fma2(wB0, v3.y, a03);
            a10 = fma2(wB1, v0.y, a10); a11 = fma2(wB1, v1.y, a11);
            a12 = fma2(wB1, v2.y, a12); a13 = fma2(wB1, v3.y, a13);
        }
        // pair-sum + publish partials: psum[e][j2][kq], e = rowhalf*4 + b
        {
            float r[8];
            float2 u;
            u = unpack2(a00); r[0] = u.x + u.y;
            u = unpack2(a01); r[1] = u.x + u.y;
            u = unpack2(a02); r[2] = u.x + u.y;
            u = unpack2(a03); r[3] = u.x + u.y;
            u = unpack2(a10); r[4] = u.x + u.y;
            u = unpack2(a11); r[5] = u.x + u.y;
            u = unpack2(a12); r[6] = u.x + u.y;
            u = unpack2(a13); r[7] = u.x + u.y;
#pragma unroll
            for (int e = 0; e < 8; ++e)
                psum[(e * 64 + j2) * 4 + kq] = r[e];
        }
        __syncthreads();

        // ---- assigned reduce + update (2 values per thread) ----
        const float4 pv0 = *(const float4*)&psum[(e0 * 64 + j2) * 4];
        const float4 pv1 = *(const float4*)&psum[((e0 + 1) * 64 + j2) * 4];
        const float z0 = (pv0.x + pv0.y) + (pv0.z + pv0.w) + biasr;
        const float z1 = (pv1.x + pv1.y) + (pv1.z + pv1.w) + biasr;
        const float th0 = ftanh(z0);
        const float th1 = ftanh(z1);
        const float hp0 = hsh[p][b0][jrow];
        const float hp1 = hsh[p][b0 + 1][jrow];
        const float h0 = fmaf(gc0, hp0 - th0, th0);   // g*h + (1-g)*tanh
        const float h1 = fmaf(gc1, hp1 - th1, th1);
        gc0 = gn0; gc1 = gn1;

        // ---- this thread's 3-way stores for its 2 values ----
        const size_t ot = (size_t)t * HH;
        po0[ot] = h0;
        po1[ot] = h1;
        if (not_last) {
            hsh[q][b0][jrow]     = h0;
            hsh[q][b0 + 1][jrow] = h1;
            const uint32_t ra0 = hr +
                (uint32_t)(((q * NB + b0) * HH + jrow) * 4);
            asm volatile("st.shared::cluster.f32 [%0], %1;"
                         :: "r"(ra0), "f"(h0) : "memory");
            asm volatile("st.shared::cluster.f32 [%0], %1;"
                         :: "r"(ra0 + (uint32_t)(HH * 4)), "f"(h1) : "memory");
        }
        __syncthreads();

        if (tid == 0 && not_last) {  // signal buffer q: local + remote arrive
            const uint32_t off = (uint32_t)q * 8u;
            asm volatile(
                "mbarrier.arrive.release.cluster.shared::cta.b64 _, [%0];"
                :: "r"(bl0 + off) : "memory");
            asm volatile(
                "mbarrier.arrive.release.cluster.shared::cluster.b64 _, [%0];"
                :: "r"(br0 + off) : "memory");
        }
    }

    // Trailing cluster sync: no CTA exits while peer DSMEM traffic may be
    // in flight toward it (exit race = unspecified launch failure).
    asm volatile("barrier.cluster.arrive.aligned;" ::: "memory");
    asm volatile("barrier.cluster.wait.aligned;"   ::: "memory");
}

// ---------------------------------------------------------------------------
extern "C" void kernel_launch(void* const* d_in, const int* in_sizes, int n_in,
                              void* d_out, int out_size)
{
    const float* x   = (const float*)d_in[0];  // [B,T,E]
    const float* Wxw = (const float*)d_in[1];  // [H,E]
    const float* Wxb = (const float*)d_in[2];  // [H]
    const float* Whw = (const float*)d_in[3];  // [H,H]
    const float* Whb = (const float*)d_in[4];  // [H]
    float* out = (float*)d_out;                // [B,T,H]

    dim3 g1(BSZ * TT / 128, HH / 128);
    gates_kernel<<<g1, 256>>>(x, Wxw, Wxb, out);

    mgu_scan<<<(BSZ / NB) * 2, 256>>>(Whw, Whb, out);
}